// round 1
// baseline (speedup 1.0000x reference)
#include <cuda_runtime.h>
#include <cuda_bf16.h>
#include <math.h>

// Problem constants
#define S_LEN   2048
#define BATCH   2
#define DMODEL  1024
#define NHEADS  16
#define DK      64
#define QB      16          // query rows per attention CTA
#define NEGV    (-1.0e9f)

#define OUT_ELEMS  ((size_t)S_LEN * BATCH * DMODEL)                 // 4,194,304
#define ATTN_ELEMS ((size_t)BATCH * NHEADS * S_LEN * S_LEN)         // 134,217,728

// ---------------- scratch (static device globals; no runtime alloc) ----------
__device__ float g_Q [BATCH * NHEADS * S_LEN * DK];
__device__ float g_K [BATCH * NHEADS * S_LEN * DK];
__device__ float g_V [BATCH * NHEADS * S_LEN * DK];
__device__ float g_HO[BATCH * NHEADS * S_LEN * DK];   // head outputs (b,h,s,d)
__device__ float g_CT[(size_t)S_LEN * BATCH * DMODEL];// context (s,b,D)

// ---------------------------------------------------------------------------
// GEMM (NT): C[m,n] = sum_k A[m,k] * W[n,k]  (+bias), A: MxK row-major,
// W: NxK row-major (nn.Linear weight). mode==1 scatters into (b,h,s,d) layout.
// Tile 64x64, BK=16, 256 threads, 4x4 per-thread micro-tile.
// ---------------------------------------------------------------------------
__global__ void __launch_bounds__(256)
gemm_nt(const float* __restrict__ A, const float* __restrict__ W,
        float* __restrict__ C, const float* __restrict__ bias,
        int M, int N, int K, int mode)
{
    __shared__ float As[16][68];
    __shared__ float Bs[16][68];

    const int tid = threadIdx.x;
    const int tx  = tid & 15;       // micro-tile col group
    const int ty  = tid >> 4;       // micro-tile row group
    const int bm  = blockIdx.y * 64;
    const int bn  = blockIdx.x * 64;

    const int lr = tid >> 2;          // 0..63 : tile row being loaded
    const int lk = (tid & 3) << 2;    // 0,4,8,12 : k offset

    const float* Ap = A + (size_t)(bm + lr) * K + lk;
    const float* Wp = W + (size_t)(bn + lr) * K + lk;

    float acc[4][4] = {};

    for (int k0 = 0; k0 < K; k0 += 16) {
        float4 a = *(const float4*)(Ap + k0);
        float4 w = *(const float4*)(Wp + k0);
        As[lk + 0][lr] = a.x; As[lk + 1][lr] = a.y;
        As[lk + 2][lr] = a.z; As[lk + 3][lr] = a.w;
        Bs[lk + 0][lr] = w.x; Bs[lk + 1][lr] = w.y;
        Bs[lk + 2][lr] = w.z; Bs[lk + 3][lr] = w.w;
        __syncthreads();

        #pragma unroll
        for (int kk = 0; kk < 16; kk++) {
            float4 av = *(const float4*)&As[kk][ty << 2];
            float4 bv = *(const float4*)&Bs[kk][tx << 2];
            acc[0][0] += av.x * bv.x; acc[0][1] += av.x * bv.y;
            acc[0][2] += av.x * bv.z; acc[0][3] += av.x * bv.w;
            acc[1][0] += av.y * bv.x; acc[1][1] += av.y * bv.y;
            acc[1][2] += av.y * bv.z; acc[1][3] += av.y * bv.w;
            acc[2][0] += av.z * bv.x; acc[2][1] += av.z * bv.y;
            acc[2][2] += av.z * bv.z; acc[2][3] += av.z * bv.w;
            acc[3][0] += av.w * bv.x; acc[3][1] += av.w * bv.y;
            acc[3][2] += av.w * bv.z; acc[3][3] += av.w * bv.w;
        }
        __syncthreads();
    }

    #pragma unroll
    for (int r = 0; r < 4; r++) {
        int m = bm + (ty << 2) + r;
        #pragma unroll
        for (int c = 0; c < 4; c++) {
            int n = bn + (tx << 2) + c;
            float v = acc[r][c];
            if (bias) v += bias[n];
            if (mode == 0) {
                C[(size_t)m * N + n] = v;
            } else {
                // m = s*BATCH + b ; n = h*DK + d  ->  (b,h,s,d)
                int s = m >> 1, b = m & 1;
                int h = n >> 6, d = n & 63;
                C[(((size_t)(b * NHEADS + h) * S_LEN) + s) * DK + d] = v;
            }
        }
    }
}

// ---------------------------------------------------------------------------
// Fused attention: one CTA per (q-block of QB rows, head, batch).
// smem: full QB x S score strip (128 KB) + Q block (4 KB).
// Phase 1: scores + masking. Phase 2: exact softmax (warp per row),
// optional attn write. Phase 3: AV from smem scores.
// ---------------------------------------------------------------------------
__global__ void __launch_bounds__(512, 1)
attn_fused(const float* __restrict__ Q, const float* __restrict__ K,
           const float* __restrict__ V,
           const int* __restrict__ mask, const int* __restrict__ kpm,
           float* __restrict__ attn_out, int write_attn,
           float* __restrict__ head_out)
{
    extern __shared__ float sm[];
    float* sc = sm;                       // QB * S_LEN
    float* qs = sm + QB * S_LEN;          // QB * DK

    const int tid = threadIdx.x;
    const int qb = blockIdx.x, h = blockIdx.y, b = blockIdx.z;
    const int q0 = qb * QB;
    const size_t bh = (size_t)(b * NHEADS + h);

    // load Q block
    const float* Qp = Q + (bh * S_LEN + q0) * DK;
    for (int i = tid; i < QB * DK; i += 512) qs[i] = Qp[i];
    __syncthreads();

    // ---- scores + masks ----
    const float* Kp   = K + bh * S_LEN * DK;
    const int*   kpmb = kpm + b * S_LEN;
    const float4* qs4 = (const float4*)qs;

    for (int k = tid; k < S_LEN; k += 512) {
        float4 kreg[16];
        const float4* krow = (const float4*)(Kp + (size_t)k * DK);
        #pragma unroll
        for (int d = 0; d < 16; d++) kreg[d] = krow[d];
        const bool kok = (kpmb[k] != 0);

        for (int i = 0; i < QB; i += 2) {
            float a0 = 0.f, a1 = 0.f;
            #pragma unroll
            for (int d = 0; d < 16; d++) {
                float4 kv = kreg[d];
                float4 q0v = qs4[i * 16 + d];
                float4 q1v = qs4[(i + 1) * 16 + d];
                a0 += q0v.x * kv.x + q0v.y * kv.y + q0v.z * kv.z + q0v.w * kv.w;
                a1 += q1v.x * kv.x + q1v.y * kv.y + q1v.z * kv.z + q1v.w * kv.w;
            }
            bool m0 = kok && (mask[(size_t)(q0 + i)     * S_LEN + k] != 0);
            bool m1 = kok && (mask[(size_t)(q0 + i + 1) * S_LEN + k] != 0);
            sc[i * S_LEN + k]       = m0 ? a0 * 0.125f : NEGV;
            sc[(i + 1) * S_LEN + k] = m1 ? a1 * 0.125f : NEGV;
        }
    }
    __syncthreads();

    // ---- softmax: warp w owns row w (16 warps, QB=16 rows) ----
    const int warp = tid >> 5, lane = tid & 31;
    {
        float* row = sc + warp * S_LEN;
        float mx = -INFINITY;
        for (int k = lane; k < S_LEN; k += 32) mx = fmaxf(mx, row[k]);
        #pragma unroll
        for (int o = 16; o; o >>= 1) mx = fmaxf(mx, __shfl_xor_sync(0xffffffffu, mx, o));

        float ssum = 0.f;
        for (int k = lane; k < S_LEN; k += 32) {
            float e = expf(row[k] - mx);
            row[k] = e;
            ssum += e;
        }
        #pragma unroll
        for (int o = 16; o; o >>= 1) ssum += __shfl_xor_sync(0xffffffffu, ssum, o);
        float inv = 1.f / ssum;

        float* arow = attn_out + ((bh * S_LEN) + q0 + warp) * (size_t)S_LEN;
        for (int k = lane; k < S_LEN; k += 32) {
            float p = row[k] * inv;
            row[k] = p;
            if (write_attn) arow[k] = p;
        }
    }
    __syncthreads();

    // ---- AV: warp w computes out row w; lane handles 2 d-columns ----
    {
        const int i = warp;                          // row 0..15
        const float2* V2 = (const float2*)(V + bh * S_LEN * DK);
        const float4* s4 = (const float4*)(sc + i * S_LEN);
        float2 acc0 = {0.f, 0.f}, acc1 = {0.f, 0.f};
        for (int k4 = 0; k4 < S_LEN / 4; k4++) {
            float4 p = s4[k4];
            float2 v0 = V2[(k4 * 4 + 0) * 32 + lane];
            float2 v1 = V2[(k4 * 4 + 1) * 32 + lane];
            float2 v2 = V2[(k4 * 4 + 2) * 32 + lane];
            float2 v3 = V2[(k4 * 4 + 3) * 32 + lane];
            acc0.x += p.x * v0.x; acc0.y += p.x * v0.y;
            acc1.x += p.y * v1.x; acc1.y += p.y * v1.y;
            acc0.x += p.z * v2.x; acc0.y += p.z * v2.y;
            acc1.x += p.w * v3.x; acc1.y += p.w * v3.y;
        }
        float2 r;
        r.x = acc0.x + acc1.x;
        r.y = acc0.y + acc1.y;
        ((float2*)(head_out + ((bh * S_LEN) + q0 + i) * DK))[lane] = r;
    }
}

// ---------------------------------------------------------------------------
// Repack (b,h,s,d) -> (s,b, h*DK+d)
// ---------------------------------------------------------------------------
__global__ void __launch_bounds__(256)
repack_heads(const float* __restrict__ ho, float* __restrict__ ctx)
{
    size_t idx = (size_t)blockIdx.x * 256 + threadIdx.x;
    if (idx >= OUT_ELEMS) return;
    int d = (int)(idx & 63);
    size_t t = idx >> 6;
    int s = (int)(t & (S_LEN - 1));
    size_t t2 = t >> 11;
    int h = (int)(t2 & (NHEADS - 1));
    int b = (int)(t2 >> 4);
    ctx[((size_t)s * BATCH + b) * DMODEL + h * DK + d] = ho[idx];
}

// ---------------------------------------------------------------------------
extern "C" void kernel_launch(void* const* d_in, const int* in_sizes, int n_in,
                              void* d_out, int out_size)
{
    const float* query = (const float*)d_in[0];
    const float* key   = (const float*)d_in[1];
    const float* value = (const float*)d_in[2];
    const int*   mask  = (const int*)  d_in[3];
    const int*   kpm   = (const int*)  d_in[4];
    const float* Wq    = (const float*)d_in[5];
    const float* Wk    = (const float*)d_in[6];
    const float* Wv    = (const float*)d_in[7];
    const float* Wo    = (const float*)d_in[8];
    const float* bo    = (const float*)d_in[9];

    float* out = (float*)d_out;
    int write_attn = ((size_t)out_size >= OUT_ELEMS + ATTN_ELEMS) ? 1 : 0;
    float* attn = out + OUT_ELEMS;   // valid only if write_attn

    float *pQ, *pK, *pV, *pHO, *pCT;
    cudaGetSymbolAddress((void**)&pQ,  g_Q);
    cudaGetSymbolAddress((void**)&pK,  g_K);
    cudaGetSymbolAddress((void**)&pV,  g_V);
    cudaGetSymbolAddress((void**)&pHO, g_HO);
    cudaGetSymbolAddress((void**)&pCT, g_CT);

    const int M = S_LEN * BATCH, N = DMODEL, Kd = DMODEL;
    dim3 gblk(256);
    dim3 ggrid(N / 64, M / 64);

    // Q/K/V projections straight into (b,h,s,d) layout
    gemm_nt<<<ggrid, gblk>>>(query, Wq, pQ, nullptr, M, N, Kd, 1);
    gemm_nt<<<ggrid, gblk>>>(key,   Wk, pK, nullptr, M, N, Kd, 1);
    gemm_nt<<<ggrid, gblk>>>(value, Wv, pV, nullptr, M, N, Kd, 1);

    // fused attention
    size_t smem = (size_t)(QB * S_LEN + QB * DK) * sizeof(float);   // 135168 B
    cudaFuncSetAttribute(attn_fused, cudaFuncAttributeMaxDynamicSharedMemorySize,
                         (int)smem);
    dim3 agrid(S_LEN / QB, NHEADS, BATCH);
    attn_fused<<<agrid, 512, smem>>>(pQ, pK, pV, mask, kpm, attn, write_attn, pHO);

    // repack + output projection (+bias)
    repack_heads<<<(unsigned)((OUT_ELEMS + 255) / 256), 256>>>(pHO, pCT);
    gemm_nt<<<ggrid, gblk>>>(pCT, Wo, out, bo, M, N, Kd, 0);
}

// round 4
// speedup vs baseline: 1.7449x; 1.7449x over previous
#include <cuda_runtime.h>
#include <cuda_bf16.h>
#include <math.h>

// ---------------- problem constants ----------------
#define S_LEN   2048
#define BATCH   2
#define DMODEL  1024
#define NHEADS  16
#define DK      64
#define NEGV    (-1.0e9f)

#define OUT_ELEMS  ((size_t)S_LEN * BATCH * DMODEL)                 // 4,194,304
#define ATTN_ELEMS ((size_t)BATCH * NHEADS * S_LEN * S_LEN)         // 134,217,728

// ---------------- scratch (static device globals; no runtime alloc) ----------
__device__ float  g_Q [BATCH * NHEADS * S_LEN * DK];
__device__ float  g_K [BATCH * NHEADS * S_LEN * DK];
__device__ float  g_KT[BATCH * NHEADS * DK * S_LEN];   // K transposed: (b,h,d,s)
__device__ float  g_V [BATCH * NHEADS * S_LEN * DK];
__device__ float  g_CT[(size_t)S_LEN * BATCH * DMODEL];// context (s,b,D)
__device__ float2 g_stats[BATCH * NHEADS * S_LEN];     // per-row {max, 1/Z}
__device__ float  g_attn_fb[ATTN_ELEMS];               // fallback scratch if attn not in output

// ---------------- cp.async helpers ----------------
__device__ __forceinline__ void cp16(const void* smem_dst, const void* gmem_src) {
    unsigned d = (unsigned)__cvta_generic_to_shared(smem_dst);
    asm volatile("cp.async.cg.shared.global [%0], [%1], 16;" :: "r"(d), "l"(gmem_src));
}
__device__ __forceinline__ void cp_commit() {
    asm volatile("cp.async.commit_group;");
}
__device__ __forceinline__ void cp_wait0() {
    asm volatile("cp.async.wait_group 0;");
}

// ===========================================================================
// GEMM (NT): C[m,n] = sum_k A[m,k] * W[n,k] (+bias).
// 128x128 tile, BK=8, 256 threads, 8x8 microtile (2x2 groups of 4x4),
// double-buffered smem, transpose-on-load.
// mode==1 scatters into (b,h,s,d) head layout.
// ===========================================================================
__global__ void __launch_bounds__(256, 2)
gemm_nt(const float* __restrict__ A, const float* __restrict__ W,
        float* __restrict__ C, const float* __restrict__ bias,
        int M, int N, int K, int mode)
{
    __shared__ __align__(16) float As[2][8][132];
    __shared__ __align__(16) float Bs[2][8][132];

    const int t  = threadIdx.x;
    const int tx = t & 15, ty = t >> 4;
    const int bm = blockIdx.y * 128;
    const int bn = blockIdx.x * 128;

    const int lrow = t >> 1;            // 0..127
    const int lk   = (t & 1) * 4;       // 0 or 4

    const float* Ap = A + (size_t)(bm + lrow) * K + lk;
    const float* Wp = W + (size_t)(bn + lrow) * K + lk;

    float acc[8][8];
    #pragma unroll
    for (int r = 0; r < 8; r++)
        #pragma unroll
        for (int c = 0; c < 8; c++) acc[r][c] = 0.f;

    float4 pa = *(const float4*)Ap;
    float4 pw = *(const float4*)Wp;
    int buf = 0;

    for (int k0 = 0; k0 < K; k0 += 8) {
        As[buf][lk + 0][lrow] = pa.x; As[buf][lk + 1][lrow] = pa.y;
        As[buf][lk + 2][lrow] = pa.z; As[buf][lk + 3][lrow] = pa.w;
        Bs[buf][lk + 0][lrow] = pw.x; Bs[buf][lk + 1][lrow] = pw.y;
        Bs[buf][lk + 2][lrow] = pw.z; Bs[buf][lk + 3][lrow] = pw.w;
        __syncthreads();

        if (k0 + 8 < K) {
            pa = *(const float4*)(Ap + k0 + 8);
            pw = *(const float4*)(Wp + k0 + 8);
        }

        #pragma unroll
        for (int kk = 0; kk < 8; kk++) {
            float4 a0 = *(const float4*)&As[buf][kk][ty * 4];
            float4 a1 = *(const float4*)&As[buf][kk][ty * 4 + 64];
            float4 b0 = *(const float4*)&Bs[buf][kk][tx * 4];
            float4 b1 = *(const float4*)&Bs[buf][kk][tx * 4 + 64];
            float av[8] = {a0.x,a0.y,a0.z,a0.w,a1.x,a1.y,a1.z,a1.w};
            float bv[8] = {b0.x,b0.y,b0.z,b0.w,b1.x,b1.y,b1.z,b1.w};
            #pragma unroll
            for (int r = 0; r < 8; r++)
                #pragma unroll
                for (int c = 0; c < 8; c++) acc[r][c] += av[r] * bv[c];
        }
        buf ^= 1;
    }

    #pragma unroll
    for (int i = 0; i < 8; i++) {
        int m = bm + ((i < 4) ? (ty * 4 + i) : (64 + ty * 4 + i - 4));
        #pragma unroll
        for (int cg = 0; cg < 2; cg++) {
            int n = bn + cg * 64 + tx * 4;
            float4 v = make_float4(acc[i][cg*4+0], acc[i][cg*4+1],
                                   acc[i][cg*4+2], acc[i][cg*4+3]);
            if (bias) {
                float4 bb = *(const float4*)(bias + n);
                v.x += bb.x; v.y += bb.y; v.z += bb.z; v.w += bb.w;
            }
            if (mode == 0) {
                *(float4*)(C + (size_t)m * N + n) = v;
            } else {
                int s = m >> 1, b = m & 1;
                int h = n >> 6, d = n & 63;
                *(float4*)(C + (((size_t)(b * NHEADS + h) * S_LEN) + s) * DK + d) = v;
            }
        }
    }
}

// ===========================================================================
// Transpose K: (b,h,s,d) -> (b,h,d,s). 32x32 tiles.
// ===========================================================================
__global__ void __launch_bounds__(256)
transpose_k(const float* __restrict__ K, float* __restrict__ KT)
{
    __shared__ float tl[32][33];
    const int bh = blockIdx.z;
    const float* src = K + (size_t)bh * S_LEN * DK;
    float*       dst = KT + (size_t)bh * DK * S_LEN;
    const int s0 = blockIdx.x * 32, d0 = blockIdx.y * 32;
    const int x = threadIdx.x, y = threadIdx.y;
    #pragma unroll
    for (int i = 0; i < 32; i += 8)
        tl[y + i][x] = src[(size_t)(s0 + y + i) * DK + d0 + x];
    __syncthreads();
    #pragma unroll
    for (int i = 0; i < 32; i += 8)
        dst[(size_t)(d0 + y + i) * S_LEN + s0 + x] = tl[x][y + i];
}

// ===========================================================================
// Pass A: scores. One CTA per (128-q tile, h, b).
// S[128q x 2048k] as GEMM over d=64; K tiles streamed via cp.async from g_KT.
// Applies masks + scale, online rowmax/Z, writes raw masked scores to attn buf
// and per-row {m, 1/Z} stats.
// ===========================================================================
#define PA_PAD 132
__global__ void __launch_bounds__(256, 2)
attn_scores(const float* __restrict__ Q, const float* __restrict__ KT,
            const int* __restrict__ mask, const int* __restrict__ kpm,
            float* __restrict__ attn, float2* __restrict__ stats)
{
    extern __shared__ __align__(16) float smA[];
    float* Qs = smA;                       // [64][132]
    float* Ks = smA + 64 * PA_PAD;         // [2][64][132]

    const int t  = threadIdx.x;
    const int tx = t & 15, ty = t >> 4;
    const int q0 = blockIdx.x * 128;
    const int h = blockIdx.y, b = blockIdx.z;
    const size_t bh = (size_t)(b * NHEADS + h);

    // load + transpose Q tile (once): Qs[d][q]
    const float* Qp = Q + (bh * S_LEN + q0) * DK;
    #pragma unroll
    for (int i = 0; i < 8; i++) {
        int f = i * 256 + t;
        int row = f >> 4, d4 = (f & 15) * 4;
        float4 v = *(const float4*)(Qp + (size_t)row * DK + d4);
        Qs[(d4 + 0) * PA_PAD + row] = v.x;
        Qs[(d4 + 1) * PA_PAD + row] = v.y;
        Qs[(d4 + 2) * PA_PAD + row] = v.z;
        Qs[(d4 + 3) * PA_PAD + row] = v.w;
    }

    const float* KTp = KT + bh * (size_t)DK * S_LEN;

    // prefetch k-tile 0 into buffer 0
    #pragma unroll
    for (int i = 0; i < 8; i++) {
        int f = i * 256 + t;
        int d = f >> 5, k4 = (f & 31) * 4;
        cp16(&Ks[d * PA_PAD + k4], KTp + (size_t)d * S_LEN + k4);
    }
    cp_commit();

    float mrow[8], zrow[8];
    #pragma unroll
    for (int i = 0; i < 8; i++) { mrow[i] = -INFINITY; zrow[i] = 0.f; }

    const int* maskp = mask + (size_t)q0 * S_LEN;
    const int* kpmb  = kpm + b * S_LEN;
    float* attnp = attn + (bh * S_LEN + q0) * S_LEN;

    for (int kt = 0; kt < 16; kt++) {
        const int buf = kt & 1;
        cp_wait0();
        __syncthreads();

        if (kt < 15) {   // stream next tile into other buffer (safe: all past sync)
            const float* KTn = KTp + (kt + 1) * 128;
            float* KsN = Ks + (buf ^ 1) * 64 * PA_PAD;
            #pragma unroll
            for (int i = 0; i < 8; i++) {
                int f = i * 256 + t;
                int d = f >> 5, k4 = (f & 31) * 4;
                cp16(&KsN[d * PA_PAD + k4], KTn + (size_t)d * S_LEN + k4);
            }
            cp_commit();
        }

        // ---- 128x128x64 GEMM ----
        float acc[8][8];
        #pragma unroll
        for (int r = 0; r < 8; r++)
            #pragma unroll
            for (int c = 0; c < 8; c++) acc[r][c] = 0.f;

        const float* KsB = Ks + buf * 64 * PA_PAD;
        #pragma unroll 8
        for (int d = 0; d < 64; d++) {
            float4 a0 = *(const float4*)&Qs [d * PA_PAD + ty * 4];
            float4 a1 = *(const float4*)&Qs [d * PA_PAD + ty * 4 + 64];
            float4 b0 = *(const float4*)&KsB[d * PA_PAD + tx * 4];
            float4 b1 = *(const float4*)&KsB[d * PA_PAD + tx * 4 + 64];
            float av[8] = {a0.x,a0.y,a0.z,a0.w,a1.x,a1.y,a1.z,a1.w};
            float bv[8] = {b0.x,b0.y,b0.z,b0.w,b1.x,b1.y,b1.z,b1.w};
            #pragma unroll
            for (int r = 0; r < 8; r++)
                #pragma unroll
                for (int c = 0; c < 8; c++) acc[r][c] += av[r] * bv[c];
        }

        // ---- epilogue: mask, scale, online stats, write raw scores ----
        const int kbase = kt * 128;
        int4 kp0 = *(const int4*)(kpmb + kbase + tx * 4);
        int4 kp1 = *(const int4*)(kpmb + kbase + tx * 4 + 64);
        bool kok[8] = { kp0.x != 0, kp0.y != 0, kp0.z != 0, kp0.w != 0,
                        kp1.x != 0, kp1.y != 0, kp1.z != 0, kp1.w != 0 };

        #pragma unroll
        for (int i = 0; i < 8; i++) {
            int q = (i < 4) ? (ty * 4 + i) : (64 + ty * 4 + i - 4);
            const int* mp = maskp + (size_t)q * S_LEN + kbase;
            int4 m0 = *(const int4*)(mp + tx * 4);
            int4 m1 = *(const int4*)(mp + tx * 4 + 64);
            float s[8];
            s[0] = (kok[0] && m0.x) ? acc[i][0] * 0.125f : NEGV;
            s[1] = (kok[1] && m0.y) ? acc[i][1] * 0.125f : NEGV;
            s[2] = (kok[2] && m0.z) ? acc[i][2] * 0.125f : NEGV;
            s[3] = (kok[3] && m0.w) ? acc[i][3] * 0.125f : NEGV;
            s[4] = (kok[4] && m1.x) ? acc[i][4] * 0.125f : NEGV;
            s[5] = (kok[5] && m1.y) ? acc[i][5] * 0.125f : NEGV;
            s[6] = (kok[6] && m1.z) ? acc[i][6] * 0.125f : NEGV;
            s[7] = (kok[7] && m1.w) ? acc[i][7] * 0.125f : NEGV;

            float mx = s[0];
            #pragma unroll
            for (int c = 1; c < 8; c++) mx = fmaxf(mx, s[c]);
            #pragma unroll
            for (int o = 8; o; o >>= 1)
                mx = fmaxf(mx, __shfl_xor_sync(0xffffffffu, mx, o));

            float mnew = fmaxf(mrow[i], mx);
            float corr = __expf(mrow[i] - mnew);
            float zl = 0.f;
            #pragma unroll
            for (int c = 0; c < 8; c++) zl += __expf(s[c] - mnew);
            #pragma unroll
            for (int o = 8; o; o >>= 1)
                zl += __shfl_xor_sync(0xffffffffu, zl, o);
            zrow[i] = zrow[i] * corr + zl;
            mrow[i] = mnew;

            float* ap = attnp + (size_t)q * S_LEN + kbase;
            *(float4*)(ap + tx * 4)      = make_float4(s[0], s[1], s[2], s[3]);
            *(float4*)(ap + tx * 4 + 64) = make_float4(s[4], s[5], s[6], s[7]);
        }
    }

    if (tx == 0) {
        #pragma unroll
        for (int i = 0; i < 8; i++) {
            int q = (i < 4) ? (ty * 4 + i) : (64 + ty * 4 + i - 4);
            stats[bh * S_LEN + q0 + q] = make_float2(mrow[i], 1.0f / zrow[i]);
        }
    }
}

// ===========================================================================
// Pass B: normalize attn in place and compute AV -> context (s,b,D).
// One CTA per (128-q tile, h, b). GEMM: out[128 x 64] = sum_k p * V.
// ===========================================================================
#define PB_PPAD 132
#define PB_VPAD 68
__global__ void __launch_bounds__(256, 2)
attn_av(const float* __restrict__ V, float* __restrict__ attn,
        const float2* __restrict__ stats, float* __restrict__ ctx)
{
    extern __shared__ __align__(16) float smB[];
    float*  Ps = smB;                            // [128][132]
    float*  Vs = smB + 128 * PB_PPAD;            // [128][68]
    float2* st = (float2*)(smB + 128 * PB_PPAD + 128 * PB_VPAD);  // [128]

    const int t  = threadIdx.x;
    const int tx = t & 7, ty = t >> 3;           // tx: d-group (8), ty: q-group (32)
    const int q0 = blockIdx.x * 128;
    const int h = blockIdx.y, b = blockIdx.z;
    const size_t bh = (size_t)(b * NHEADS + h);

    if (t < 128) st[t] = stats[bh * S_LEN + q0 + t];

    float* attnp   = attn + (bh * S_LEN + q0) * S_LEN;
    const float* Vp = V + bh * (size_t)S_LEN * DK;

    float acc[4][8];
    #pragma unroll
    for (int r = 0; r < 4; r++)
        #pragma unroll
        for (int c = 0; c < 8; c++) acc[r][c] = 0.f;

    for (int kt = 0; kt < 16; kt++) {
        __syncthreads();   // prev-iteration compute done (also orders st on kt=0)

        // V tile via cp.async: Vs[k][d]
        const float* Vt = Vp + (size_t)kt * 128 * DK;
        #pragma unroll
        for (int i = 0; i < 8; i++) {
            int f = i * 256 + t;
            int row = f >> 4, d4 = (f & 15) * 4;
            cp16(&Vs[row * PB_VPAD + d4], Vt + (size_t)row * DK + d4);
        }
        cp_commit();

        // score tile -> p (normalize), write back to gmem + stage in smem
        #pragma unroll
        for (int i = 0; i < 16; i++) {
            int f = i * 256 + t;
            int row = f >> 5, k4 = (f & 31) * 4;
            float* gp = attnp + (size_t)row * S_LEN + kt * 128 + k4;
            float4 s4 = *(const float4*)gp;
            float2 mz = st[row];
            float4 p4;
            p4.x = __expf(s4.x - mz.x) * mz.y;
            p4.y = __expf(s4.y - mz.x) * mz.y;
            p4.z = __expf(s4.z - mz.x) * mz.y;
            p4.w = __expf(s4.w - mz.x) * mz.y;
            *(float4*)gp = p4;
            *(float4*)&Ps[row * PB_PPAD + k4] = p4;
        }
        cp_wait0();
        __syncthreads();

        #pragma unroll 4
        for (int kk = 0; kk < 128; kk++) {
            float pv[4];
            pv[0] = Ps[(ty * 4 + 0) * PB_PPAD + kk];
            pv[1] = Ps[(ty * 4 + 1) * PB_PPAD + kk];
            pv[2] = Ps[(ty * 4 + 2) * PB_PPAD + kk];
            pv[3] = Ps[(ty * 4 + 3) * PB_PPAD + kk];
            float4 v0 = *(const float4*)&Vs[kk * PB_VPAD + tx * 4];
            float4 v1 = *(const float4*)&Vs[kk * PB_VPAD + 32 + tx * 4];
            float vv[8] = {v0.x,v0.y,v0.z,v0.w,v1.x,v1.y,v1.z,v1.w};
            #pragma unroll
            for (int r = 0; r < 4; r++)
                #pragma unroll
                for (int c = 0; c < 8; c++) acc[r][c] += pv[r] * vv[c];
        }
    }

    // write context rows (s,b,D) directly
    #pragma unroll
    for (int r = 0; r < 4; r++) {
        int q = q0 + ty * 4 + r;
        float* cp_ = ctx + ((size_t)q * BATCH + b) * DMODEL + h * DK;
        *(float4*)(cp_ + tx * 4)      = make_float4(acc[r][0], acc[r][1], acc[r][2], acc[r][3]);
        *(float4*)(cp_ + 32 + tx * 4) = make_float4(acc[r][4], acc[r][5], acc[r][6], acc[r][7]);
    }
}

// ===========================================================================
extern "C" void kernel_launch(void* const* d_in, const int* in_sizes, int n_in,
                              void* d_out, int out_size)
{
    const float* query = (const float*)d_in[0];
    const float* key   = (const float*)d_in[1];
    const float* value = (const float*)d_in[2];
    const int*   mask  = (const int*)  d_in[3];
    const int*   kpm   = (const int*)  d_in[4];
    const float* Wq    = (const float*)d_in[5];
    const float* Wk    = (const float*)d_in[6];
    const float* Wv    = (const float*)d_in[7];
    const float* Wo    = (const float*)d_in[8];
    const float* bo    = (const float*)d_in[9];

    float* out = (float*)d_out;
    const int write_attn = ((size_t)out_size >= OUT_ELEMS + ATTN_ELEMS) ? 1 : 0;

    float *pQ, *pK, *pKT, *pV, *pCT, *pAfb;
    float2* pST;
    cudaGetSymbolAddress((void**)&pQ,   g_Q);
    cudaGetSymbolAddress((void**)&pK,   g_K);
    cudaGetSymbolAddress((void**)&pKT,  g_KT);
    cudaGetSymbolAddress((void**)&pV,   g_V);
    cudaGetSymbolAddress((void**)&pCT,  g_CT);
    cudaGetSymbolAddress((void**)&pST,  g_stats);
    cudaGetSymbolAddress((void**)&pAfb, g_attn_fb);

    float* attn = write_attn ? (out + OUT_ELEMS) : pAfb;

    const int M = S_LEN * BATCH, N = DMODEL, Kd = DMODEL;
    dim3 gblk(256);
    dim3 ggrid(N / 128, M / 128);

    // projections into (b,h,s,d)
    gemm_nt<<<ggrid, gblk>>>(query, Wq, pQ, nullptr, M, N, Kd, 1);
    gemm_nt<<<ggrid, gblk>>>(key,   Wk, pK, nullptr, M, N, Kd, 1);
    gemm_nt<<<ggrid, gblk>>>(value, Wv, pV, nullptr, M, N, Kd, 1);

    // K -> d-major
    transpose_k<<<dim3(S_LEN / 32, DK / 32, BATCH * NHEADS), dim3(32, 8)>>>(pK, pKT);

    // pass A: scores + online stats
    const int smA_bytes = (64 * PA_PAD + 2 * 64 * PA_PAD) * 4;           // 101376
    cudaFuncSetAttribute(attn_scores, cudaFuncAttributeMaxDynamicSharedMemorySize, smA_bytes);
    dim3 agrid(S_LEN / 128, NHEADS, BATCH);
    attn_scores<<<agrid, 256, smA_bytes>>>(pQ, pKT, mask, kpm, attn, pST);

    // pass B: normalize + AV -> context
    const int smB_bytes = (128 * PB_PPAD + 128 * PB_VPAD + 256) * 4;     // 103424
    cudaFuncSetAttribute(attn_av, cudaFuncAttributeMaxDynamicSharedMemorySize, smB_bytes);
    attn_av<<<agrid, 256, smB_bytes>>>(pV, attn, pST, pCT);

    // output projection (+bias)
    gemm_nt<<<ggrid, gblk>>>(pCT, Wo, out, bo, M, N, Kd, 0);
}

// round 5
// speedup vs baseline: 2.0544x; 1.1774x over previous
#include <cuda_runtime.h>
#include <cuda_bf16.h>
#include <math.h>

// ---------------- problem constants ----------------
#define S_LEN   2048
#define BATCH   2
#define DMODEL  1024
#define NHEADS  16
#define DK      64
#define NEGV    (-1.0e9f)

#define OUT_ELEMS  ((size_t)S_LEN * BATCH * DMODEL)                 // 4,194,304
#define ATTN_ELEMS ((size_t)BATCH * NHEADS * S_LEN * S_LEN)         // 134,217,728

typedef __nv_bfloat16  bf16;
typedef __nv_bfloat162 bf162;

// ---------------- scratch (static device globals; no runtime alloc) ----------
__device__ bf16  g_Xs [(size_t)4096 * 3072];   // split activations [hi|hi|lo]
__device__ bf16  g_Ws [(size_t)1024 * 3072];   // split weights     [hi|lo|hi]
__device__ bf16  g_Qhi[(size_t)32 * 2048 * 64];
__device__ bf16  g_Qlo[(size_t)32 * 2048 * 64];
__device__ bf16  g_Khi[(size_t)32 * 2048 * 64];
__device__ bf16  g_Klo[(size_t)32 * 2048 * 64];
__device__ bf16  g_Vhi[(size_t)32 * 2048 * 64];
__device__ bf16  g_Vlo[(size_t)32 * 2048 * 64];
__device__ bf16  g_VThi[(size_t)32 * 64 * 2048];
__device__ bf16  g_VTlo[(size_t)32 * 64 * 2048];
__device__ float g_CT[(size_t)4096 * 1024];    // context (s,b,D)
__device__ float2 g_stats[32 * 2048];          // per-row {max, 1/Z}
__device__ float g_attn_fb[ATTN_ELEMS];        // fallback if attn not in output

// ---------------- PTX helpers ----------------
__device__ __forceinline__ void cp16(const void* smem_dst, const void* gmem_src) {
    unsigned d = (unsigned)__cvta_generic_to_shared(smem_dst);
    asm volatile("cp.async.cg.shared.global [%0], [%1], 16;" :: "r"(d), "l"(gmem_src));
}
__device__ __forceinline__ void cp_commit() { asm volatile("cp.async.commit_group;"); }
__device__ __forceinline__ void cp_wait0()  { asm volatile("cp.async.wait_group 0;"); }

__device__ __forceinline__ void mma_bf16(float& d0, float& d1, float& d2, float& d3,
                                         unsigned a0, unsigned a1, unsigned a2, unsigned a3,
                                         unsigned b0, unsigned b1)
{
    asm volatile(
        "mma.sync.aligned.m16n8k16.row.col.f32.bf16.bf16.f32 "
        "{%0,%1,%2,%3},{%4,%5,%6,%7},{%8,%9},{%0,%1,%2,%3};\n"
        : "+f"(d0), "+f"(d1), "+f"(d2), "+f"(d3)
        : "r"(a0), "r"(a1), "r"(a2), "r"(a3), "r"(b0), "r"(b1));
}

// ===========================================================================
// prep_split: fp32 (rows x 1024) -> bf16 (rows x 3072) augmented-K split.
// pattern 0 (activations): [hi | hi | lo]
// pattern 1 (weights):     [hi | lo | hi]
// ===========================================================================
__global__ void __launch_bounds__(256)
prep_split(const float* __restrict__ src, bf16* __restrict__ dst,
           int rows, int pattern)
{
    size_t p = (size_t)blockIdx.x * 256 + threadIdx.x;
    size_t total = (size_t)rows * 512;
    if (p >= total) return;
    int row = (int)(p >> 9);
    int cp  = (int)(p & 511);
    float2 v = *(const float2*)(src + (size_t)row * 1024 + cp * 2);
    bf16 h0 = __float2bfloat16_rn(v.x);
    bf16 h1 = __float2bfloat16_rn(v.y);
    bf16 l0 = __float2bfloat16_rn(v.x - __bfloat162float(h0));
    bf16 l1 = __float2bfloat16_rn(v.y - __bfloat162float(h1));
    bf162 h2; h2.x = h0; h2.y = h1;
    bf162 l2; l2.x = l0; l2.y = l1;
    bf162* d = (bf162*)(dst + (size_t)row * 3072 + cp * 2);
    if (pattern == 0) { d[0] = h2; d[512] = h2; d[1024] = l2; }
    else              { d[0] = h2; d[512] = l2; d[1024] = h2; }
}

// ===========================================================================
// gemm_bf16: C[m,n] = sum_k A[m,k]*B[n,k], A: Mx K bf16, B: N x K bf16 (NT).
// BM=BN=128, BK=32, 256 thr = 8 warps, warp = 16 rows x 128 cols.
// mode 0: fp32 C (+bias). mode 1: split-bf16 scatter into (b,h,s,d) pair.
// ===========================================================================
#define GP 40   // padded K-stride in bf16 elems (80B, 16B-aligned, conflict-free)
__global__ void __launch_bounds__(256)
gemm_bf16(const bf16* __restrict__ A, const bf16* __restrict__ B,
          int M, int N, int K, int mode,
          float* __restrict__ C, const float* __restrict__ bias,
          bf16* __restrict__ Dhi, bf16* __restrict__ Dlo)
{
    __shared__ __align__(16) bf16 sA[2][128 * GP];
    __shared__ __align__(16) bf16 sB[2][128 * GP];

    const int t = threadIdx.x;
    const int wid = t >> 5, lane = t & 31;
    const int r0 = lane >> 2, c0 = (lane & 3) * 2;
    const int bm = blockIdx.y * 128, bn = blockIdx.x * 128;

    float acc[16][4];
    #pragma unroll
    for (int i = 0; i < 16; i++)
        #pragma unroll
        for (int j = 0; j < 4; j++) acc[i][j] = 0.f;

    // tile loader: 512 chunks(16B) per matrix, 2 per thread
    #pragma unroll
    for (int i = 0; i < 2; i++) {
        int f = i * 256 + t; int row = f >> 2, ck = f & 3;
        cp16(&sA[0][row * GP + ck * 8], A + (size_t)(bm + row) * K + ck * 8);
        cp16(&sB[0][row * GP + ck * 8], B + (size_t)(bn + row) * K + ck * 8);
    }
    cp_commit();

    const int ntk = K / 32;
    int buf = 0;
    for (int kt = 0; kt < ntk; kt++) {
        cp_wait0();
        __syncthreads();
        if (kt + 1 < ntk) {
            int k0 = (kt + 1) * 32;
            #pragma unroll
            for (int i = 0; i < 2; i++) {
                int f = i * 256 + t; int row = f >> 2, ck = f & 3;
                cp16(&sA[buf ^ 1][row * GP + ck * 8], A + (size_t)(bm + row) * K + k0 + ck * 8);
                cp16(&sB[buf ^ 1][row * GP + ck * 8], B + (size_t)(bn + row) * K + k0 + ck * 8);
            }
            cp_commit();
        }

        const bf16* a = &sA[buf][(wid * 16) * GP];
        const bf16* bsm = &sB[buf][0];
        #pragma unroll
        for (int ks = 0; ks < 2; ks++) {
            const int kk = ks * 16;
            unsigned a0 = *(const unsigned*)&a[(r0    ) * GP + kk + c0];
            unsigned a1 = *(const unsigned*)&a[(r0 + 8) * GP + kk + c0];
            unsigned a2 = *(const unsigned*)&a[(r0    ) * GP + kk + c0 + 8];
            unsigned a3 = *(const unsigned*)&a[(r0 + 8) * GP + kk + c0 + 8];
            #pragma unroll
            for (int nt = 0; nt < 16; nt++) {
                unsigned b0 = *(const unsigned*)&bsm[(nt * 8 + r0) * GP + kk + c0];
                unsigned b1 = *(const unsigned*)&bsm[(nt * 8 + r0) * GP + kk + c0 + 8];
                mma_bf16(acc[nt][0], acc[nt][1], acc[nt][2], acc[nt][3],
                         a0, a1, a2, a3, b0, b1);
            }
        }
        buf ^= 1;
    }

    const int mA = bm + wid * 16 + r0, mB = mA + 8;
    #pragma unroll
    for (int nt = 0; nt < 16; nt++) {
        int n = bn + nt * 8 + c0;
        if (mode == 0) {
            float bx = bias ? bias[n] : 0.f, by = bias ? bias[n + 1] : 0.f;
            *(float2*)(C + (size_t)mA * N + n) = make_float2(acc[nt][0] + bx, acc[nt][1] + by);
            *(float2*)(C + (size_t)mB * N + n) = make_float2(acc[nt][2] + bx, acc[nt][3] + by);
        } else {
            int h = n >> 6, d = n & 63;
            #pragma unroll
            for (int rr = 0; rr < 2; rr++) {
                int m = rr ? mB : mA;
                float v0 = acc[nt][rr * 2], v1 = acc[nt][rr * 2 + 1];
                int s = m >> 1, b = m & 1;
                size_t off = (((size_t)(b * NHEADS + h) * S_LEN) + s) * 64 + d;
                bf16 h0 = __float2bfloat16_rn(v0);
                bf16 h1 = __float2bfloat16_rn(v1);
                bf16 l0 = __float2bfloat16_rn(v0 - __bfloat162float(h0));
                bf16 l1 = __float2bfloat16_rn(v1 - __bfloat162float(h1));
                bf162 h2; h2.x = h0; h2.y = h1;
                bf162 l2; l2.x = l0; l2.y = l1;
                *(bf162*)(Dhi + off) = h2;
                *(bf162*)(Dlo + off) = l2;
            }
        }
    }
}

// ===========================================================================
// transpose_bf16: (b,h,s,64) -> (b,h,64,2048)
// ===========================================================================
__global__ void __launch_bounds__(256)
transpose_bf16(const bf16* __restrict__ src, bf16* __restrict__ dst)
{
    __shared__ bf16 tl[32][34];
    const int bh = blockIdx.z;
    const bf16* s = src + (size_t)bh * 2048 * 64;
    bf16*       d = dst + (size_t)bh * 64 * 2048;
    const int s0 = blockIdx.x * 32, d0 = blockIdx.y * 32;
    const int x = threadIdx.x, y = threadIdx.y;
    #pragma unroll
    for (int i = 0; i < 32; i += 8)
        tl[y + i][x] = s[(size_t)(s0 + y + i) * 64 + d0 + x];
    __syncthreads();
    #pragma unroll
    for (int i = 0; i < 32; i += 8)
        d[(size_t)(d0 + y + i) * 2048 + s0 + x] = tl[x][y + i];
}

// ===========================================================================
// qk_scores: per CTA (128 q rows, h, b): 3-product bf16 MMA over d=64,
// mask + scale + online softmax stats, raw masked scores -> attn buffer.
// warp = 16 rows x 128 cols (row stats stay within one warp).
// ===========================================================================
#define QP 72   // padded K-stride (144B, 16B-aligned; banks 4r+c conflict-free)
__global__ void __launch_bounds__(256)
qk_scores(const bf16* __restrict__ Qhi, const bf16* __restrict__ Qlo,
          const bf16* __restrict__ Khi, const bf16* __restrict__ Klo,
          const int* __restrict__ mask, const int* __restrict__ kpm,
          float* __restrict__ attn, float2* __restrict__ stats)
{
    extern __shared__ __align__(16) bf16 smq[];
    bf16* sQh = smq;                 // 128*72
    bf16* sQl = smq + 9216;
    bf16* sK  = smq + 18432;         // [buf][hi/lo][128*72]

    const int t = threadIdx.x;
    const int wid = t >> 5, lane = t & 31;
    const int r0 = lane >> 2, c0 = (lane & 3) * 2;
    const int q0 = blockIdx.x * 128, h = blockIdx.y, b = blockIdx.z;
    const size_t bh = (size_t)(b * NHEADS + h);

    // load Q tiles (once)
    {
        const size_t base = bh * 2048 + q0;
        #pragma unroll
        for (int i = 0; i < 4; i++) {
            int f = i * 256 + t; int row = f >> 3, ck = f & 7;
            cp16(&sQh[row * QP + ck * 8], Qhi + (base + row) * 64 + ck * 8);
            cp16(&sQl[row * QP + ck * 8], Qlo + (base + row) * 64 + ck * 8);
        }
    }
    // load K tile 0
    {
        const size_t base = bh * 2048;
        #pragma unroll
        for (int i = 0; i < 4; i++) {
            int f = i * 256 + t; int row = f >> 3, ck = f & 7;
            cp16(&sK[0 * 9216 + row * QP + ck * 8], Khi + (base + row) * 64 + ck * 8);
            cp16(&sK[1 * 9216 + row * QP + ck * 8], Klo + (base + row) * 64 + ck * 8);
        }
    }
    cp_commit();

    float mrA = -INFINITY, zrA = 0.f, mrB = -INFINITY, zrB = 0.f;
    const int qA = q0 + wid * 16 + r0;
    const int* maskA = mask + (size_t)qA * S_LEN;
    const int* maskB = maskA + (size_t)8 * S_LEN;
    const int* kpmb  = kpm + b * S_LEN;
    float* attnA = attn + (bh * S_LEN + qA) * (size_t)S_LEN;
    float* attnB = attnA + (size_t)8 * S_LEN;

    int buf = 0;
    for (int kt = 0; kt < 16; kt++) {
        cp_wait0();
        __syncthreads();
        if (kt < 15) {
            const size_t base = bh * 2048 + (size_t)(kt + 1) * 128;
            bf16* dh = sK + ((buf ^ 1) * 2 + 0) * 9216;
            bf16* dl = sK + ((buf ^ 1) * 2 + 1) * 9216;
            #pragma unroll
            for (int i = 0; i < 4; i++) {
                int f = i * 256 + t; int row = f >> 3, ck = f & 7;
                cp16(&dh[row * QP + ck * 8], Khi + (base + row) * 64 + ck * 8);
                cp16(&dl[row * QP + ck * 8], Klo + (base + row) * 64 + ck * 8);
            }
            cp_commit();
        }

        float acc[16][4];
        #pragma unroll
        for (int i = 0; i < 16; i++)
            #pragma unroll
            for (int j = 0; j < 4; j++) acc[i][j] = 0.f;

        #pragma unroll
        for (int pr = 0; pr < 3; pr++) {
            const bf16* Aop = (pr < 2) ? sQh : sQl;
            const bf16* Bop = sK + (buf * 2 + (pr == 1 ? 1 : 0)) * 9216;
            const bf16* a = Aop + (wid * 16) * QP;
            #pragma unroll
            for (int ks = 0; ks < 4; ks++) {
                const int kk = ks * 16;
                unsigned a0 = *(const unsigned*)&a[(r0    ) * QP + kk + c0];
                unsigned a1 = *(const unsigned*)&a[(r0 + 8) * QP + kk + c0];
                unsigned a2 = *(const unsigned*)&a[(r0    ) * QP + kk + c0 + 8];
                unsigned a3 = *(const unsigned*)&a[(r0 + 8) * QP + kk + c0 + 8];
                #pragma unroll
                for (int nt = 0; nt < 16; nt++) {
                    unsigned b0 = *(const unsigned*)&Bop[(nt * 8 + r0) * QP + kk + c0];
                    unsigned b1 = *(const unsigned*)&Bop[(nt * 8 + r0) * QP + kk + c0 + 8];
                    mma_bf16(acc[nt][0], acc[nt][1], acc[nt][2], acc[nt][3],
                             a0, a1, a2, a3, b0, b1);
                }
            }
        }

        // epilogue: mask + scale + online stats + raw score store
        const int kbase = kt * 128;
        float tmA = -INFINITY, tmB = -INFINITY;
        #pragma unroll
        for (int nt = 0; nt < 16; nt++) {
            int kg = kbase + nt * 8 + c0;
            int2 kp = *(const int2*)&kpmb[kg];
            int2 ma = *(const int2*)&maskA[kg];
            int2 mb = *(const int2*)&maskB[kg];
            float v0 = (kp.x && ma.x) ? acc[nt][0] * 0.125f : NEGV;
            float v1 = (kp.y && ma.y) ? acc[nt][1] * 0.125f : NEGV;
            float v2 = (kp.x && mb.x) ? acc[nt][2] * 0.125f : NEGV;
            float v3 = (kp.y && mb.y) ? acc[nt][3] * 0.125f : NEGV;
            acc[nt][0] = v0; acc[nt][1] = v1; acc[nt][2] = v2; acc[nt][3] = v3;
            tmA = fmaxf(tmA, fmaxf(v0, v1));
            tmB = fmaxf(tmB, fmaxf(v2, v3));
        }
        tmA = fmaxf(tmA, __shfl_xor_sync(0xffffffffu, tmA, 1));
        tmA = fmaxf(tmA, __shfl_xor_sync(0xffffffffu, tmA, 2));
        tmB = fmaxf(tmB, __shfl_xor_sync(0xffffffffu, tmB, 1));
        tmB = fmaxf(tmB, __shfl_xor_sync(0xffffffffu, tmB, 2));

        float mnA = fmaxf(mrA, tmA), mnB = fmaxf(mrB, tmB);
        float corA = __expf(mrA - mnA), corB = __expf(mrB - mnB);
        float zlA = 0.f, zlB = 0.f;
        #pragma unroll
        for (int nt = 0; nt < 16; nt++) {
            zlA += __expf(acc[nt][0] - mnA) + __expf(acc[nt][1] - mnA);
            zlB += __expf(acc[nt][2] - mnB) + __expf(acc[nt][3] - mnB);
        }
        zlA += __shfl_xor_sync(0xffffffffu, zlA, 1);
        zlA += __shfl_xor_sync(0xffffffffu, zlA, 2);
        zlB += __shfl_xor_sync(0xffffffffu, zlB, 1);
        zlB += __shfl_xor_sync(0xffffffffu, zlB, 2);
        zrA = zrA * corA + zlA; mrA = mnA;
        zrB = zrB * corB + zlB; mrB = mnB;

        #pragma unroll
        for (int nt = 0; nt < 16; nt++) {
            int kg = kbase + nt * 8 + c0;
            *(float2*)&attnA[kg] = make_float2(acc[nt][0], acc[nt][1]);
            *(float2*)&attnB[kg] = make_float2(acc[nt][2], acc[nt][3]);
        }
        buf ^= 1;
    }

    if ((lane & 3) == 0) {
        stats[bh * S_LEN + qA]     = make_float2(mrA, 1.f / zrA);
        stats[bh * S_LEN + qA + 8] = make_float2(mrB, 1.f / zrB);
    }
}

// ===========================================================================
// attn_av: per CTA (128 q, h, b): normalize P in place (required attn output),
// split P on the fly into bf16 hi/lo smem; 3-product MMA with VT hi/lo tiles;
// ctx written directly in (s,b,D) layout.
// ===========================================================================
#define PP 136  // padded K-stride (272B, 16B-aligned; banks 4r+c conflict-free)
__global__ void __launch_bounds__(256)
attn_av(const bf16* __restrict__ VThi, const bf16* __restrict__ VTlo,
        float* __restrict__ attn, const float2* __restrict__ stats,
        float* __restrict__ ctx)
{
    extern __shared__ __align__(16) bf16 smv[];
    bf16* sPh = smv;                  // 128*136 = 17408
    bf16* sPl = smv + 17408;
    bf16* sVh = smv + 34816;          // 64*136 = 8704
    bf16* sVl = smv + 43520;
    float2* st = (float2*)(smv + 52224);   // 128 entries

    const int t = threadIdx.x;
    const int wid = t >> 5, lane = t & 31;
    const int r0 = lane >> 2, c0 = (lane & 3) * 2;
    const int q0 = blockIdx.x * 128, h = blockIdx.y, b = blockIdx.z;
    const size_t bh = (size_t)(b * NHEADS + h);

    if (t < 128) st[t] = stats[bh * S_LEN + q0 + t];

    float* attnp = attn + (bh * S_LEN + q0) * (size_t)S_LEN;
    const bf16* Vh = VThi + bh * (size_t)64 * 2048;
    const bf16* Vl = VTlo + bh * (size_t)64 * 2048;

    float acc[8][4];
    #pragma unroll
    for (int i = 0; i < 8; i++)
        #pragma unroll
        for (int j = 0; j < 4; j++) acc[i][j] = 0.f;

    for (int kt = 0; kt < 16; kt++) {
        __syncthreads();   // prev compute done; st visible at kt=0

        // V tiles via cp.async
        #pragma unroll
        for (int i = 0; i < 4; i++) {
            int f = i * 256 + t; int row = f >> 4, ck = f & 15;
            cp16(&sVh[row * PP + ck * 8], Vh + (size_t)row * 2048 + kt * 128 + ck * 8);
            cp16(&sVl[row * PP + ck * 8], Vl + (size_t)row * 2048 + kt * 128 + ck * 8);
        }
        cp_commit();

        // normalize P tile, write back, split into smem
        #pragma unroll
        for (int i = 0; i < 16; i++) {
            int f = i * 256 + t; int row = f >> 5, k4 = (f & 31) * 4;
            float* gp = attnp + (size_t)row * S_LEN + kt * 128 + k4;
            float4 s4 = *(const float4*)gp;
            float2 mz = st[row];
            float4 p4;
            p4.x = __expf(s4.x - mz.x) * mz.y;
            p4.y = __expf(s4.y - mz.x) * mz.y;
            p4.z = __expf(s4.z - mz.x) * mz.y;
            p4.w = __expf(s4.w - mz.x) * mz.y;
            *(float4*)gp = p4;
            bf16 h0 = __float2bfloat16_rn(p4.x), h1 = __float2bfloat16_rn(p4.y);
            bf16 h2 = __float2bfloat16_rn(p4.z), h3 = __float2bfloat16_rn(p4.w);
            bf162 ha; ha.x = h0; ha.y = h1;
            bf162 hb; hb.x = h2; hb.y = h3;
            bf162 la; la.x = __float2bfloat16_rn(p4.x - __bfloat162float(h0));
                      la.y = __float2bfloat16_rn(p4.y - __bfloat162float(h1));
            bf162 lb; lb.x = __float2bfloat16_rn(p4.z - __bfloat162float(h2));
                      lb.y = __float2bfloat16_rn(p4.w - __bfloat162float(h3));
            *(bf162*)&sPh[row * PP + k4]     = ha;
            *(bf162*)&sPh[row * PP + k4 + 2] = hb;
            *(bf162*)&sPl[row * PP + k4]     = la;
            *(bf162*)&sPl[row * PP + k4 + 2] = lb;
        }
        cp_wait0();
        __syncthreads();

        #pragma unroll
        for (int pr = 0; pr < 3; pr++) {
            const bf16* Aop = (pr < 2) ? sPh : sPl;
            const bf16* Bop = (pr == 1) ? sVl : sVh;
            const bf16* a = Aop + (wid * 16) * PP;
            #pragma unroll
            for (int ks = 0; ks < 8; ks++) {
                const int kk = ks * 16;
                unsigned a0 = *(const unsigned*)&a[(r0    ) * PP + kk + c0];
                unsigned a1 = *(const unsigned*)&a[(r0 + 8) * PP + kk + c0];
                unsigned a2 = *(const unsigned*)&a[(r0    ) * PP + kk + c0 + 8];
                unsigned a3 = *(const unsigned*)&a[(r0 + 8) * PP + kk + c0 + 8];
                #pragma unroll
                for (int nt = 0; nt < 8; nt++) {
                    unsigned b0 = *(const unsigned*)&Bop[(nt * 8 + r0) * PP + kk + c0];
                    unsigned b1 = *(const unsigned*)&Bop[(nt * 8 + r0) * PP + kk + c0 + 8];
                    mma_bf16(acc[nt][0], acc[nt][1], acc[nt][2], acc[nt][3],
                             a0, a1, a2, a3, b0, b1);
                }
            }
        }
    }

    // write context (s,b,D)
    const int qA = q0 + wid * 16 + r0, qB = qA + 8;
    #pragma unroll
    for (int nt = 0; nt < 8; nt++) {
        int d = h * 64 + nt * 8 + c0;
        *(float2*)&ctx[((size_t)qA * BATCH + b) * DMODEL + d] =
            make_float2(acc[nt][0], acc[nt][1]);
        *(float2*)&ctx[((size_t)qB * BATCH + b) * DMODEL + d] =
            make_float2(acc[nt][2], acc[nt][3]);
    }
}

// ===========================================================================
extern "C" void kernel_launch(void* const* d_in, const int* in_sizes, int n_in,
                              void* d_out, int out_size)
{
    const float* query = (const float*)d_in[0];
    const float* key   = (const float*)d_in[1];
    const float* value = (const float*)d_in[2];
    const int*   mask  = (const int*)  d_in[3];
    const int*   kpm   = (const int*)  d_in[4];
    const float* Wq    = (const float*)d_in[5];
    const float* Wk    = (const float*)d_in[6];
    const float* Wv    = (const float*)d_in[7];
    const float* Wo    = (const float*)d_in[8];
    const float* bo    = (const float*)d_in[9];

    float* out = (float*)d_out;
    const int write_attn = ((size_t)out_size >= OUT_ELEMS + ATTN_ELEMS) ? 1 : 0;

    bf16 *pXs, *pWs, *pQh, *pQl, *pKh, *pKl, *pVh, *pVl, *pVTh, *pVTl;
    float *pCT, *pAfb;
    float2* pST;
    cudaGetSymbolAddress((void**)&pXs,  g_Xs);
    cudaGetSymbolAddress((void**)&pWs,  g_Ws);
    cudaGetSymbolAddress((void**)&pQh,  g_Qhi);
    cudaGetSymbolAddress((void**)&pQl,  g_Qlo);
    cudaGetSymbolAddress((void**)&pKh,  g_Khi);
    cudaGetSymbolAddress((void**)&pKl,  g_Klo);
    cudaGetSymbolAddress((void**)&pVh,  g_Vhi);
    cudaGetSymbolAddress((void**)&pVl,  g_Vlo);
    cudaGetSymbolAddress((void**)&pVTh, g_VThi);
    cudaGetSymbolAddress((void**)&pVTl, g_VTlo);
    cudaGetSymbolAddress((void**)&pCT,  g_CT);
    cudaGetSymbolAddress((void**)&pST,  g_stats);
    cudaGetSymbolAddress((void**)&pAfb, g_attn_fb);

    float* attn = write_attn ? (out + OUT_ELEMS) : pAfb;

    const int M = S_LEN * BATCH;     // 4096
    dim3 ggrid(1024 / 128, M / 128); // (8, 32)
    const unsigned px_blocks = (unsigned)(((size_t)M * 512 + 255) / 256);
    const unsigned pw_blocks = (unsigned)(((size_t)1024 * 512 + 255) / 256);

    // Q projection
    prep_split<<<px_blocks, 256>>>(query, pXs, M, 0);
    prep_split<<<pw_blocks, 256>>>(Wq, pWs, 1024, 1);
    gemm_bf16<<<ggrid, 256>>>(pXs, pWs, M, 1024, 3072, 1, nullptr, nullptr, pQh, pQl);
    // K projection
    prep_split<<<px_blocks, 256>>>(key, pXs, M, 0);
    prep_split<<<pw_blocks, 256>>>(Wk, pWs, 1024, 1);
    gemm_bf16<<<ggrid, 256>>>(pXs, pWs, M, 1024, 3072, 1, nullptr, nullptr, pKh, pKl);
    // V projection
    prep_split<<<px_blocks, 256>>>(value, pXs, M, 0);
    prep_split<<<pw_blocks, 256>>>(Wv, pWs, 1024, 1);
    gemm_bf16<<<ggrid, 256>>>(pXs, pWs, M, 1024, 3072, 1, nullptr, nullptr, pVh, pVl);

    // V -> d-major
    dim3 tgrid(2048 / 32, 64 / 32, 32);
    transpose_bf16<<<tgrid, dim3(32, 8)>>>(pVh, pVTh);
    transpose_bf16<<<tgrid, dim3(32, 8)>>>(pVl, pVTl);

    // QK^T + masks + online stats
    const int smq_bytes = 55296 * 2;          // 110592
    cudaFuncSetAttribute(qk_scores, cudaFuncAttributeMaxDynamicSharedMemorySize, smq_bytes);
    dim3 agrid(S_LEN / 128, NHEADS, BATCH);
    qk_scores<<<agrid, 256, smq_bytes>>>(pQh, pQl, pKh, pKl, mask, kpm, attn, pST);

    // normalize + AV -> ctx
    const int smv_bytes = 52224 * 2 + 128 * 8; // 105472
    cudaFuncSetAttribute(attn_av, cudaFuncAttributeMaxDynamicSharedMemorySize, smv_bytes);
    attn_av<<<agrid, 256, smv_bytes>>>(pVTh, pVTl, attn, pST, pCT);

    // output projection (+bias)
    prep_split<<<px_blocks, 256>>>(pCT, pXs, M, 0);
    prep_split<<<pw_blocks, 256>>>(Wo, pWs, 1024, 1);
    gemm_bf16<<<ggrid, 256>>>(pXs, pWs, M, 1024, 3072, 0, out, bo, nullptr, nullptr);
}

// round 7
// speedup vs baseline: 2.1469x; 1.0450x over previous
#include <cuda_runtime.h>
#include <cuda_bf16.h>
#include <math.h>

// ---------------- problem constants ----------------
#define S_LEN   2048
#define BATCH   2
#define DMODEL  1024
#define NHEADS  16
#define DK      64
#define NEGV    (-1.0e9f)

#define OUT_ELEMS  ((size_t)S_LEN * BATCH * DMODEL)                 // 4,194,304
#define ATTN_ELEMS ((size_t)BATCH * NHEADS * S_LEN * S_LEN)         // 134,217,728

typedef __nv_bfloat16  bf16;
typedef __nv_bfloat162 bf162;

#define XS_SLAB ((size_t)4096 * 3072)
#define WS_SLAB ((size_t)1024 * 3072)

// ---------------- scratch (static device globals; no runtime alloc) ----------
__device__ bf16  g_Xs [3 * XS_SLAB];           // split activations [hi|hi|lo] x {q,k,v / ctx}
__device__ bf16  g_Ws [4 * WS_SLAB];           // split weights     [hi|lo|hi] x {Wq,Wk,Wv,Wo}
__device__ bf16  g_Qhi[(size_t)32 * 2048 * 64];
__device__ bf16  g_Qlo[(size_t)32 * 2048 * 64];
__device__ bf16  g_Khi[(size_t)32 * 2048 * 64];
__device__ bf16  g_Klo[(size_t)32 * 2048 * 64];
__device__ bf16  g_Vhi[(size_t)32 * 2048 * 64];
__device__ bf16  g_Vlo[(size_t)32 * 2048 * 64];
__device__ bf16  g_VThi[(size_t)32 * 64 * 2048];
__device__ bf16  g_VTlo[(size_t)32 * 64 * 2048];
__device__ float g_CT[(size_t)4096 * 1024];    // context (s,b,D)
__device__ float2 g_stats[32 * 2048];          // per-row {max, 1/Z}
__device__ float g_attn_fb[ATTN_ELEMS];        // fallback if attn not in output

// ---------------- PTX helpers ----------------
__device__ __forceinline__ void cp16(const void* smem_dst, const void* gmem_src) {
    unsigned d = (unsigned)__cvta_generic_to_shared(smem_dst);
    asm volatile("cp.async.cg.shared.global [%0], [%1], 16;" :: "r"(d), "l"(gmem_src));
}
__device__ __forceinline__ void cp_commit() { asm volatile("cp.async.commit_group;"); }
__device__ __forceinline__ void cp_wait0()  { asm volatile("cp.async.wait_group 0;"); }

__device__ __forceinline__ unsigned smem_u32(const void* p) {
    return (unsigned)__cvta_generic_to_shared(p);
}

__device__ __forceinline__ void mma_bf16(float& d0, float& d1, float& d2, float& d3,
                                         unsigned a0, unsigned a1, unsigned a2, unsigned a3,
                                         unsigned b0, unsigned b1)
{
    asm volatile(
        "mma.sync.aligned.m16n8k16.row.col.f32.bf16.bf16.f32 "
        "{%0,%1,%2,%3},{%4,%5,%6,%7},{%8,%9},{%0,%1,%2,%3};\n"
        : "+f"(d0), "+f"(d1), "+f"(d2), "+f"(d3)
        : "r"(a0), "r"(a1), "r"(a2), "r"(a3), "r"(b0), "r"(b1));
}

__device__ __forceinline__ void ldsm4(unsigned& r0, unsigned& r1, unsigned& r2, unsigned& r3,
                                      unsigned addr)
{
    asm volatile("ldmatrix.sync.aligned.m8n8.x4.shared.b16 {%0,%1,%2,%3}, [%4];"
                 : "=r"(r0), "=r"(r1), "=r"(r2), "=r"(r3) : "r"(addr));
}

// ===========================================================================
// prep kernels: fp32 (rows x 1024) -> bf16 (rows x 3072) augmented-K split.
// pattern 0 (activations): [hi | hi | lo]   pattern 1 (weights): [hi | lo | hi]
// ===========================================================================
__device__ __forceinline__ void split_store(const float* src, bf16* dst,
                                            size_t p, int pattern)
{
    int row = (int)(p >> 9);
    int cp  = (int)(p & 511);
    float2 v = *(const float2*)(src + (size_t)row * 1024 + cp * 2);
    bf16 h0 = __float2bfloat16_rn(v.x);
    bf16 h1 = __float2bfloat16_rn(v.y);
    bf16 l0 = __float2bfloat16_rn(v.x - __bfloat162float(h0));
    bf16 l1 = __float2bfloat16_rn(v.y - __bfloat162float(h1));
    bf162 h2; h2.x = h0; h2.y = h1;
    bf162 l2; l2.x = l0; l2.y = l1;
    bf162* d = (bf162*)(dst + (size_t)row * 3072 + cp * 2);
    if (pattern == 0) { d[0] = h2; d[512] = h2; d[1024] = l2; }
    else              { d[0] = h2; d[512] = l2; d[1024] = h2; }
}

__global__ void __launch_bounds__(256)
prep_qkv(const float* __restrict__ q, const float* __restrict__ k,
         const float* __restrict__ v, bf16* __restrict__ dst)
{
    size_t p = (size_t)blockIdx.x * 256 + threadIdx.x;
    if (p >= (size_t)4096 * 512) return;
    const float* src = (blockIdx.z == 0) ? q : (blockIdx.z == 1) ? k : v;
    split_store(src, dst + blockIdx.z * XS_SLAB, p, 0);
}

__global__ void __launch_bounds__(256)
prep_w(const float* __restrict__ w0, const float* __restrict__ w1,
       const float* __restrict__ w2, const float* __restrict__ w3,
       bf16* __restrict__ dst)
{
    size_t p = (size_t)blockIdx.x * 256 + threadIdx.x;
    if (p >= (size_t)1024 * 512) return;
    const float* src = (blockIdx.z == 0) ? w0 : (blockIdx.z == 1) ? w1
                     : (blockIdx.z == 2) ? w2 : w3;
    split_store(src, dst + blockIdx.z * WS_SLAB, p, 1);
}

__global__ void __launch_bounds__(256)
prep_one(const float* __restrict__ src, bf16* __restrict__ dst, int rows)
{
    size_t p = (size_t)blockIdx.x * 256 + threadIdx.x;
    if (p >= (size_t)rows * 512) return;
    split_store(src, dst, p, 0);
}

// ===========================================================================
// gemm_bf16: C[m,n] = sum_k A[m,k]*B[n,k], NT, K=3072, 128x128 tile, BK=32,
// 256 thr = 8 warps, warp = 16 rows x 128 cols, ldmatrix fragment loads.
// mode 0: fp32 C (+bias). mode 1: split-bf16 scatter into (b,h,s,d).
// ===========================================================================
#define GP 40   // padded K-stride (80B = 5x16B units, odd -> conflict-free ldmatrix)
__global__ void __launch_bounds__(256)
gemm_bf16(const bf16* __restrict__ A, const bf16* __restrict__ B,
          int mode, float* __restrict__ C, const float* __restrict__ bias,
          bf16* __restrict__ Dhi, bf16* __restrict__ Dlo)
{
    __shared__ __align__(16) bf16 sA[2][128 * GP];
    __shared__ __align__(16) bf16 sB[2][128 * GP];

    const int t = threadIdx.x;
    const int wid = t >> 5, lane = t & 31;
    const int r0 = lane >> 2, c0 = (lane & 3) * 2;
    const int g  = lane >> 3, lr = lane & 7;       // ldmatrix group / row-in-group
    const int bm = blockIdx.y * 128, bn = blockIdx.x * 128;
    const int K = 3072;

    float acc[16][4];
    #pragma unroll
    for (int i = 0; i < 16; i++)
        #pragma unroll
        for (int j = 0; j < 4; j++) acc[i][j] = 0.f;

    // loader indices: 512 16B-chunks per matrix, 2 per thread
    #pragma unroll
    for (int i = 0; i < 2; i++) {
        int f = i * 256 + t; int row = f >> 2, ck = f & 3;
        cp16(&sA[0][row * GP + ck * 8], A + (size_t)(bm + row) * K + ck * 8);
        cp16(&sB[0][row * GP + ck * 8], B + (size_t)(bn + row) * K + ck * 8);
    }
    cp_commit();

    const unsigned uA0 = smem_u32(&sA[0][0]), uA1 = smem_u32(&sA[1][0]);
    const unsigned uB0 = smem_u32(&sB[0][0]), uB1 = smem_u32(&sB[1][0]);

    int buf = 0;
    for (int kt = 0; kt < K / 32; kt++) {
        cp_wait0();
        __syncthreads();
        if (kt + 1 < K / 32) {
            int k0 = (kt + 1) * 32;
            #pragma unroll
            for (int i = 0; i < 2; i++) {
                int f = i * 256 + t; int row = f >> 2, ck = f & 3;
                cp16(&sA[buf ^ 1][row * GP + ck * 8], A + (size_t)(bm + row) * K + k0 + ck * 8);
                cp16(&sB[buf ^ 1][row * GP + ck * 8], B + (size_t)(bn + row) * K + k0 + ck * 8);
            }
            cp_commit();
        }

        const unsigned uA = buf ? uA1 : uA0;
        const unsigned uB = buf ? uB1 : uB0;
        #pragma unroll
        for (int ks = 0; ks < 2; ks++) {
            const int kk = ks * 16;
            unsigned a0, a1, a2, a3;
            ldsm4(a0, a1, a2, a3,
                  uA + (unsigned)(((wid * 16 + (g & 1) * 8 + lr) * GP + kk + (g >> 1) * 8) * 2));
            #pragma unroll
            for (int p = 0; p < 8; p++) {
                unsigned b0, b1, b2, b3;
                ldsm4(b0, b1, b2, b3,
                      uB + (unsigned)(((p * 16 + (g >> 1) * 8 + lr) * GP + kk + (g & 1) * 8) * 2));
                mma_bf16(acc[2*p][0], acc[2*p][1], acc[2*p][2], acc[2*p][3],
                         a0, a1, a2, a3, b0, b1);
                mma_bf16(acc[2*p+1][0], acc[2*p+1][1], acc[2*p+1][2], acc[2*p+1][3],
                         a0, a1, a2, a3, b2, b3);
            }
        }
        __syncthreads();
        buf ^= 1;
    }

    const int mA = bm + wid * 16 + r0, mB = mA + 8;
    #pragma unroll
    for (int nt = 0; nt < 16; nt++) {
        int n = bn + nt * 8 + c0;
        if (mode == 0) {
            float bx = bias[n], by = bias[n + 1];
            *(float2*)(C + (size_t)mA * 1024 + n) = make_float2(acc[nt][0] + bx, acc[nt][1] + by);
            *(float2*)(C + (size_t)mB * 1024 + n) = make_float2(acc[nt][2] + bx, acc[nt][3] + by);
        } else {
            int h = n >> 6, d = n & 63;
            #pragma unroll
            for (int rr = 0; rr < 2; rr++) {
                int m = rr ? mB : mA;
                float v0 = acc[nt][rr * 2], v1 = acc[nt][rr * 2 + 1];
                int s = m >> 1, b = m & 1;
                size_t off = (((size_t)(b * NHEADS + h) * S_LEN) + s) * 64 + d;
                bf16 h0 = __float2bfloat16_rn(v0);
                bf16 h1 = __float2bfloat16_rn(v1);
                bf16 l0 = __float2bfloat16_rn(v0 - __bfloat162float(h0));
                bf16 l1 = __float2bfloat16_rn(v1 - __bfloat162float(h1));
                bf162 hh; hh.x = h0; hh.y = h1;
                bf162 ll; ll.x = l0; ll.y = l1;
                *(bf162*)(Dhi + off) = hh;
                *(bf162*)(Dlo + off) = ll;
            }
        }
    }
}

// ===========================================================================
// transpose_bf16: (b,h,s,64) -> (b,h,64,2048)
// ===========================================================================
__global__ void __launch_bounds__(256)
transpose_bf16(const bf16* __restrict__ src, bf16* __restrict__ dst)
{
    __shared__ bf16 tl[32][34];
    const int bh = blockIdx.z;
    const bf16* s = src + (size_t)bh * 2048 * 64;
    bf16*       d = dst + (size_t)bh * 64 * 2048;
    const int s0 = blockIdx.x * 32, d0 = blockIdx.y * 32;
    const int x = threadIdx.x, y = threadIdx.y;
    #pragma unroll
    for (int i = 0; i < 32; i += 8)
        tl[y + i][x] = s[(size_t)(s0 + y + i) * 64 + d0 + x];
    __syncthreads();
    #pragma unroll
    for (int i = 0; i < 32; i += 8)
        d[(size_t)(d0 + y + i) * 2048 + s0 + x] = tl[x][y + i];
}

// ===========================================================================
// qk_scores: per CTA (128 q rows, h, b): 3-product bf16 MMA over d=64,
// mask + scale + online softmax stats, raw masked scores -> attn buffer.
// ===========================================================================
#define QP 72   // 144B = 9x16B units, odd -> conflict-free ldmatrix
__global__ void __launch_bounds__(256)
qk_scores(const bf16* __restrict__ Qhi, const bf16* __restrict__ Qlo,
          const bf16* __restrict__ Khi, const bf16* __restrict__ Klo,
          const int* __restrict__ mask, const int* __restrict__ kpm,
          float* __restrict__ attn, float2* __restrict__ stats)
{
    extern __shared__ __align__(16) bf16 smq[];
    bf16* sQh = smq;
    bf16* sQl = smq + 9216;
    bf16* sK  = smq + 18432;

    const int t = threadIdx.x;
    const int wid = t >> 5, lane = t & 31;
    const int r0 = lane >> 2, c0 = (lane & 3) * 2;
    const int g  = lane >> 3, lr = lane & 7;
    const int q0 = blockIdx.x * 128, h = blockIdx.y, b = blockIdx.z;
    const size_t bh = (size_t)(b * NHEADS + h);

    {
        const size_t base = bh * 2048 + q0;
        #pragma unroll
        for (int i = 0; i < 4; i++) {
            int f = i * 256 + t; int row = f >> 3, ck = f & 7;
            cp16(&sQh[row * QP + ck * 8], Qhi + (base + row) * 64 + ck * 8);
            cp16(&sQl[row * QP + ck * 8], Qlo + (base + row) * 64 + ck * 8);
        }
    }
    {
        const size_t base = bh * 2048;
        #pragma unroll
        for (int i = 0; i < 4; i++) {
            int f = i * 256 + t; int row = f >> 3, ck = f & 7;
            cp16(&sK[0 * 9216 + row * QP + ck * 8], Khi + (base + row) * 64 + ck * 8);
            cp16(&sK[1 * 9216 + row * QP + ck * 8], Klo + (base + row) * 64 + ck * 8);
        }
    }
    cp_commit();

    const unsigned uQh = smem_u32(sQh), uQl = smem_u32(sQl), uK = smem_u32(sK);

    float mrA = -INFINITY, zrA = 0.f, mrB = -INFINITY, zrB = 0.f;
    const int qA = q0 + wid * 16 + r0;
    const int* maskA = mask + (size_t)qA * S_LEN;
    const int* maskB = maskA + (size_t)8 * S_LEN;
    const int* kpmb  = kpm + b * S_LEN;
    float* attnA = attn + (bh * S_LEN + qA) * (size_t)S_LEN;
    float* attnB = attnA + (size_t)8 * S_LEN;

    // ldmatrix per-lane offsets (in elements)
    const int aoff = (wid * 16 + (g & 1) * 8 + lr) * QP + (g >> 1) * 8;
    const int boff_row = (g >> 1) * 8 + lr;
    const int boff_k   = (g & 1) * 8;

    int buf = 0;
    for (int kt = 0; kt < 16; kt++) {
        cp_wait0();
        __syncthreads();
        if (kt < 15) {
            const size_t base = bh * 2048 + (size_t)(kt + 1) * 128;
            bf16* dh = sK + ((buf ^ 1) * 2 + 0) * 9216;
            bf16* dl = sK + ((buf ^ 1) * 2 + 1) * 9216;
            #pragma unroll
            for (int i = 0; i < 4; i++) {
                int f = i * 256 + t; int row = f >> 3, ck = f & 7;
                cp16(&dh[row * QP + ck * 8], Khi + (base + row) * 64 + ck * 8);
                cp16(&dl[row * QP + ck * 8], Klo + (base + row) * 64 + ck * 8);
            }
            cp_commit();
        }

        float acc[16][4];
        #pragma unroll
        for (int i = 0; i < 16; i++)
            #pragma unroll
            for (int j = 0; j < 4; j++) acc[i][j] = 0.f;

        #pragma unroll
        for (int pr = 0; pr < 3; pr++) {
            const unsigned aU = (pr < 2) ? uQh : uQl;
            const unsigned bU = uK + (unsigned)(((buf * 2 + (pr == 1 ? 1 : 0)) * 9216) * 2);
            #pragma unroll
            for (int ks = 0; ks < 4; ks++) {
                const int kk = ks * 16;
                unsigned a0, a1, a2, a3;
                ldsm4(a0, a1, a2, a3, aU + (unsigned)((aoff + kk) * 2));
                #pragma unroll
                for (int p = 0; p < 8; p++) {
                    unsigned b0, b1, b2, b3;
                    ldsm4(b0, b1, b2, b3,
                          bU + (unsigned)(((p * 16 + boff_row) * QP + kk + boff_k) * 2));
                    mma_bf16(acc[2*p][0], acc[2*p][1], acc[2*p][2], acc[2*p][3],
                             a0, a1, a2, a3, b0, b1);
                    mma_bf16(acc[2*p+1][0], acc[2*p+1][1], acc[2*p+1][2], acc[2*p+1][3],
                             a0, a1, a2, a3, b2, b3);
                }
            }
        }

        const int kbase = kt * 128;
        float tmA = -INFINITY, tmB = -INFINITY;
        #pragma unroll
        for (int nt = 0; nt < 16; nt++) {
            int kg = kbase + nt * 8 + c0;
            int2 kp = *(const int2*)&kpmb[kg];
            int2 ma = *(const int2*)&maskA[kg];
            int2 mb = *(const int2*)&maskB[kg];
            float v0 = (kp.x && ma.x) ? acc[nt][0] * 0.125f : NEGV;
            float v1 = (kp.y && ma.y) ? acc[nt][1] * 0.125f : NEGV;
            float v2 = (kp.x && mb.x) ? acc[nt][2] * 0.125f : NEGV;
            float v3 = (kp.y && mb.y) ? acc[nt][3] * 0.125f : NEGV;
            acc[nt][0] = v0; acc[nt][1] = v1; acc[nt][2] = v2; acc[nt][3] = v3;
            tmA = fmaxf(tmA, fmaxf(v0, v1));
            tmB = fmaxf(tmB, fmaxf(v2, v3));
        }
        tmA = fmaxf(tmA, __shfl_xor_sync(0xffffffffu, tmA, 1));
        tmA = fmaxf(tmA, __shfl_xor_sync(0xffffffffu, tmA, 2));
        tmB = fmaxf(tmB, __shfl_xor_sync(0xffffffffu, tmB, 1));
        tmB = fmaxf(tmB, __shfl_xor_sync(0xffffffffu, tmB, 2));

        float mnA = fmaxf(mrA, tmA), mnB = fmaxf(mrB, tmB);
        float corA = __expf(mrA - mnA), corB = __expf(mrB - mnB);
        float zlA = 0.f, zlB = 0.f;
        #pragma unroll
        for (int nt = 0; nt < 16; nt++) {
            zlA += __expf(acc[nt][0] - mnA) + __expf(acc[nt][1] - mnA);
            zlB += __expf(acc[nt][2] - mnB) + __expf(acc[nt][3] - mnB);
        }
        zlA += __shfl_xor_sync(0xffffffffu, zlA, 1);
        zlA += __shfl_xor_sync(0xffffffffu, zlA, 2);
        zlB += __shfl_xor_sync(0xffffffffu, zlB, 1);
        zlB += __shfl_xor_sync(0xffffffffu, zlB, 2);
        zrA = zrA * corA + zlA; mrA = mnA;
        zrB = zrB * corB + zlB; mrB = mnB;

        #pragma unroll
        for (int nt = 0; nt < 16; nt++) {
            int kg = kbase + nt * 8 + c0;
            *(float2*)&attnA[kg] = make_float2(acc[nt][0], acc[nt][1]);
            *(float2*)&attnB[kg] = make_float2(acc[nt][2], acc[nt][3]);
        }
        buf ^= 1;
    }

    if ((lane & 3) == 0) {
        stats[bh * S_LEN + qA]     = make_float2(mrA, 1.f / zrA);
        stats[bh * S_LEN + qA + 8] = make_float2(mrB, 1.f / zrB);
    }
}

// ===========================================================================
// attn_av: normalize P in place (required attn output), split P to bf16 hi/lo
// smem, 3-product ldmatrix MMA with VT hi/lo tiles, ctx written in (s,b,D).
// ===========================================================================
#define PP 136  // 272B = 17x16B units, odd -> conflict-free ldmatrix
__global__ void __launch_bounds__(256)
attn_av(const bf16* __restrict__ VThi, const bf16* __restrict__ VTlo,
        float* __restrict__ attn, const float2* __restrict__ stats,
        float* __restrict__ ctx)
{
    extern __shared__ __align__(16) bf16 smv[];
    bf16* sPh = smv;
    bf16* sPl = smv + 17408;
    bf16* sVh = smv + 34816;
    bf16* sVl = smv + 43520;
    float2* st = (float2*)(smv + 52224);

    const int t = threadIdx.x;
    const int wid = t >> 5, lane = t & 31;
    const int r0 = lane >> 2, c0 = (lane & 3) * 2;
    const int g  = lane >> 3, lr = lane & 7;
    const int q0 = blockIdx.x * 128, h = blockIdx.y, b = blockIdx.z;
    const size_t bh = (size_t)(b * NHEADS + h);

    if (t < 128) st[t] = stats[bh * S_LEN + q0 + t];

    float* attnp = attn + (bh * S_LEN + q0) * (size_t)S_LEN;
    const bf16* Vh = VThi + bh * (size_t)64 * 2048;
    const bf16* Vl = VTlo + bh * (size_t)64 * 2048;

    const unsigned uPh = smem_u32(sPh), uPl = smem_u32(sPl);
    const unsigned uVh = smem_u32(sVh), uVl = smem_u32(sVl);
    const int aoff = (wid * 16 + (g & 1) * 8 + lr) * PP + (g >> 1) * 8;
    const int boff_row = (g >> 1) * 8 + lr;
    const int boff_k   = (g & 1) * 8;

    float acc[8][4];
    #pragma unroll
    for (int i = 0; i < 8; i++)
        #pragma unroll
        for (int j = 0; j < 4; j++) acc[i][j] = 0.f;

    for (int kt = 0; kt < 16; kt++) {
        __syncthreads();

        #pragma unroll
        for (int i = 0; i < 4; i++) {
            int f = i * 256 + t; int row = f >> 4, ck = f & 15;
            cp16(&sVh[row * PP + ck * 8], Vh + (size_t)row * 2048 + kt * 128 + ck * 8);
            cp16(&sVl[row * PP + ck * 8], Vl + (size_t)row * 2048 + kt * 128 + ck * 8);
        }
        cp_commit();

        #pragma unroll
        for (int i = 0; i < 16; i++) {
            int f = i * 256 + t; int row = f >> 5, k4 = (f & 31) * 4;
            float* gp = attnp + (size_t)row * S_LEN + kt * 128 + k4;
            float4 s4 = *(const float4*)gp;
            float2 mz = st[row];
            float4 p4;
            p4.x = __expf(s4.x - mz.x) * mz.y;
            p4.y = __expf(s4.y - mz.x) * mz.y;
            p4.z = __expf(s4.z - mz.x) * mz.y;
            p4.w = __expf(s4.w - mz.x) * mz.y;
            *(float4*)gp = p4;
            bf16 h0 = __float2bfloat16_rn(p4.x), h1 = __float2bfloat16_rn(p4.y);
            bf16 h2 = __float2bfloat16_rn(p4.z), h3 = __float2bfloat16_rn(p4.w);
            bf162 ha; ha.x = h0; ha.y = h1;
            bf162 hb; hb.x = h2; hb.y = h3;
            bf162 la; la.x = __float2bfloat16_rn(p4.x - __bfloat162float(h0));
                      la.y = __float2bfloat16_rn(p4.y - __bfloat162float(h1));
            bf162 lb; lb.x = __float2bfloat16_rn(p4.z - __bfloat162float(h2));
                      lb.y = __float2bfloat16_rn(p4.w - __bfloat162float(h3));
            *(bf162*)&sPh[row * PP + k4]     = ha;
            *(bf162*)&sPh[row * PP + k4 + 2] = hb;
            *(bf162*)&sPl[row * PP + k4]     = la;
            *(bf162*)&sPl[row * PP + k4 + 2] = lb;
        }
        cp_wait0();
        __syncthreads();

        #pragma unroll
        for (int pr = 0; pr < 3; pr++) {
            const unsigned aU = (pr < 2) ? uPh : uPl;
            const unsigned bU = (pr == 1) ? uVl : uVh;
            #pragma unroll
            for (int ks = 0; ks < 8; ks++) {
                const int kk = ks * 16;
                unsigned a0, a1, a2, a3;
                ldsm4(a0, a1, a2, a3, aU + (unsigned)((aoff + kk) * 2));
                #pragma unroll
                for (int p = 0; p < 4; p++) {
                    unsigned b0, b1, b2, b3;
                    ldsm4(b0, b1, b2, b3,
                          bU + (unsigned)(((p * 16 + boff_row) * PP + kk + boff_k) * 2));
                    mma_bf16(acc[2*p][0], acc[2*p][1], acc[2*p][2], acc[2*p][3],
                             a0, a1, a2, a3, b0, b1);
                    mma_bf16(acc[2*p+1][0], acc[2*p+1][1], acc[2*p+1][2], acc[2*p+1][3],
                             a0, a1, a2, a3, b2, b3);
                }
            }
        }
    }

    const int qA = q0 + wid * 16 + r0, qB = qA + 8;
    #pragma unroll
    for (int nt = 0; nt < 8; nt++) {
        int d = h * 64 + nt * 8 + c0;
        *(float2*)&ctx[((size_t)qA * BATCH + b) * DMODEL + d] =
            make_float2(acc[nt][0], acc[nt][1]);
        *(float2*)&ctx[((size_t)qB * BATCH + b) * DMODEL + d] =
            make_float2(acc[nt][2], acc[nt][3]);
    }
}

// ===========================================================================
extern "C" void kernel_launch(void* const* d_in, const int* in_sizes, int n_in,
                              void* d_out, int out_size)
{
    const float* query = (const float*)d_in[0];
    const float* key   = (const float*)d_in[1];
    const float* value = (const float*)d_in[2];
    const int*   mask  = (const int*)  d_in[3];
    const int*   kpm   = (const int*)  d_in[4];
    const float* Wq    = (const float*)d_in[5];
    const float* Wk    = (const float*)d_in[6];
    const float* Wv    = (const float*)d_in[7];
    const float* Wo    = (const float*)d_in[8];
    const float* bo    = (const float*)d_in[9];

    float* out = (float*)d_out;
    const int write_attn = ((size_t)out_size >= OUT_ELEMS + ATTN_ELEMS) ? 1 : 0;

    bf16 *pXs, *pWs, *pQh, *pQl, *pKh, *pKl, *pVh, *pVl, *pVTh, *pVTl;
    float *pCT, *pAfb;
    float2* pST;
    cudaGetSymbolAddress((void**)&pXs,  g_Xs);
    cudaGetSymbolAddress((void**)&pWs,  g_Ws);
    cudaGetSymbolAddress((void**)&pQh,  g_Qhi);
    cudaGetSymbolAddress((void**)&pQl,  g_Qlo);
    cudaGetSymbolAddress((void**)&pKh,  g_Khi);
    cudaGetSymbolAddress((void**)&pKl,  g_Klo);
    cudaGetSymbolAddress((void**)&pVh,  g_Vhi);
    cudaGetSymbolAddress((void**)&pVl,  g_Vlo);
    cudaGetSymbolAddress((void**)&pVTh, g_VThi);
    cudaGetSymbolAddress((void**)&pVTl, g_VTlo);
    cudaGetSymbolAddress((void**)&pCT,  g_CT);
    cudaGetSymbolAddress((void**)&pST,  g_stats);
    cudaGetSymbolAddress((void**)&pAfb, g_attn_fb);

    float* attn = write_attn ? (out + OUT_ELEMS) : pAfb;

    const int M = S_LEN * BATCH;     // 4096
    dim3 ggrid(1024 / 128, M / 128); // (8, 32)

    // batched splits: all 4 weights; q,k,v activations
    prep_w  <<<dim3(2048, 1, 4), 256>>>(Wq, Wk, Wv, Wo, pWs);
    prep_qkv<<<dim3(8192, 1, 3), 256>>>(query, key, value, pXs);

    // projections into (b,h,s,d) split layout
    gemm_bf16<<<ggrid, 256>>>(pXs,              pWs,              1, nullptr, nullptr, pQh, pQl);
    gemm_bf16<<<ggrid, 256>>>(pXs + XS_SLAB,    pWs + WS_SLAB,    1, nullptr, nullptr, pKh, pKl);
    gemm_bf16<<<ggrid, 256>>>(pXs + 2*XS_SLAB,  pWs + 2*WS_SLAB,  1, nullptr, nullptr, pVh, pVl);

    // V -> d-major
    dim3 tgrid(2048 / 32, 64 / 32, 32);
    transpose_bf16<<<tgrid, dim3(32, 8)>>>(pVh, pVTh);
    transpose_bf16<<<tgrid, dim3(32, 8)>>>(pVl, pVTl);

    // QK^T + masks + online stats
    const int smq_bytes = 55296 * 2;
    cudaFuncSetAttribute(qk_scores, cudaFuncAttributeMaxDynamicSharedMemorySize, smq_bytes);
    dim3 agrid(S_LEN / 128, NHEADS, BATCH);
    qk_scores<<<agrid, 256, smq_bytes>>>(pQh, pQl, pKh, pKl, mask, kpm, attn, pST);

    // normalize + AV -> ctx
    const int smv_bytes = 52224 * 2 + 128 * 8;
    cudaFuncSetAttribute(attn_av, cudaFuncAttributeMaxDynamicSharedMemorySize, smv_bytes);
    attn_av<<<agrid, 256, smv_bytes>>>(pVTh, pVTl, attn, pST, pCT);

    // output projection (+bias)
    prep_one<<<8192, 256>>>(pCT, pXs, M);
    gemm_bf16<<<ggrid, 256>>>(pXs, pWs + 3*WS_SLAB, 0, out, bo, nullptr, nullptr);
}